// round 10
// baseline (speedup 1.0000x reference)
#include <cuda_runtime.h>
#include <cstddef>

// Problem constants (fixed-shape benchmark)
#define VV   2048
#define NN   16
#define DI   32
#define DO   64
#define NH   8
#define NT   1152          // tasks = H*12*12
#define CID  192           // DI*6
#define EDIM 2496          // 32*13*6
#define MROW 29952         // 12*EDIM
#define PN   32768         // VV*16
#define KA_ELEMS (DO*VV*6)     // 786432
#define FM_ELEMS (DI*VV*6)     // 393216

typedef unsigned long long u64;
typedef unsigned int u32;

// ---------------- helpers ----------------
__device__ __forceinline__ u64 bc2(float x) {
    u64 r; asm("mov.b64 %0,{%1,%1};" : "=l"(r) : "f"(x)); return r;
}
__device__ __forceinline__ void up2(float& x, float& y, u64 v) {
    asm("mov.b64 {%0,%1},%2;" : "=f"(x), "=f"(y) : "l"(v));
}
__device__ __forceinline__ void fma2(u64& d, u64 a, u64 b) {
    asm("fma.rn.f32x2 %0,%1,%2,%0;" : "+l"(d) : "l"(a), "l"(b));
}
__device__ __forceinline__ float tf32r(float x) {
    u32 r; asm("cvt.rna.tf32.f32 %0,%1;" : "=r"(r) : "f"(x));
    return __uint_as_float(r);
}
__device__ __forceinline__ void mma_tf32(float c[4], u32 a0, u32 a1, u32 a2, u32 a3,
                                         u32 b0, u32 b1) {
    asm volatile("mma.sync.aligned.m16n8k8.row.col.f32.tf32.tf32.f32 "
                 "{%0,%1,%2,%3}, {%4,%5,%6,%7}, {%8,%9}, {%0,%1,%2,%3};"
                 : "+f"(c[0]), "+f"(c[1]), "+f"(c[2]), "+f"(c[3])
                 : "r"(a0), "r"(a1), "r"(a2), "r"(a3), "r"(b0), "r"(b1));
}

// ---------------- constant tables ----------------
__constant__ int cINV[12][6] = {
    {0,1,2,3,4,5},{0,5,4,3,2,1},{4,3,0,5,2,1},{1,2,4,3,5,0},
    {3,5,2,0,4,1},{1,4,3,5,0,2},{4,0,3,1,2,5},{1,0,2,4,3,5},
    {4,1,2,5,0,3},{3,1,4,0,2,5},{2,1,4,5,3,0},{4,5,0,3,1,2}};
__constant__ int cROLL[5][6] = {
    {0,1,2,3,4,5},{0,2,3,4,5,1},{0,3,4,5,1,2},{0,4,5,1,2,3},{0,5,1,2,3,4}};
__constant__ int cC2V[6][2] = {{0,1},{6,7},{2,11},{4,9},{5,8},{3,10}};
#define PHI 1.6180339887498949f
__constant__ float cVSU[12][3] = {
    {0.f,1.f,PHI},{0.f,1.f,-PHI},{0.f,-1.f,PHI},{0.f,-1.f,-PHI},
    {1.f,PHI,0.f},{1.f,-PHI,0.f},{-1.f,PHI,0.f},{-1.f,-PHI,0.f},
    {PHI,0.f,1.f},{PHI,0.f,-1.f},{-PHI,0.f,1.f},{-PHI,0.f,-1.f}};

// ---------------- device scratch ----------------
__device__ float g_Wdr[CID * NT];                 // [ci][task], tf32-rounded, 0.5 folded
__device__ float g_Wg[12 * DO * EDIM];            // [r][d][e] (tf32-rounded)
__device__ float g_cross[(size_t)CID * PN];       // [ci][p*16+n]  full fp32
__device__ float g_M[(size_t)VV * MROW];          // [p][r][e]
__device__ float g_feat[12 * DO * VV];            // [r][d][p]

// ---------------- symmetry expansion ----------------
__device__ __forceinline__ float w13v(const float* Wp, int k, int j) {
    if (k == 0)  return (j == 0) ? Wp[0] : Wp[1];
    if (k == 1)  return (j == 0) ? Wp[2] : Wp[3];
    if (k == 12) return (j == 0) ? Wp[4] : Wp[5];
    if (k < 7)   return Wp[6  + cROLL[k - 2][j]];
    return               Wp[12 + cROLL[k - 7][j]];
}

__global__ void prepWdr(const float* __restrict__ Wdir) {
    int idx = blockIdx.x * blockDim.x + threadIdx.x;
    if (idx >= CID * NT) return;
    int t = idx % NT, ci = idx / NT;
    int c = ci / 6, i = ci % 6;
    int h = t / 144, k = (t / 12) % 12, r = t % 12;
    const float* Wp = Wdir + (h * 32 + c) * 18;
    g_Wdr[idx] = tf32r(0.5f * w13v(Wp, k, cINV[r][i]));
}

__global__ void prepWg(const float* __restrict__ W) {
    int idx = blockIdx.x * blockDim.x + threadIdx.x;
    if (idx >= 12 * DO * EDIM) return;
    int e = idx % EDIM;
    int d = (idx / EDIM) % DO;
    int r = idx / (EDIM * DO);
    int c = e / 78, rem = e % 78, k = rem / 6, i = rem % 6;
    const float* Wp = W + (d * 32 + c) * 18;
    g_Wg[idx] = tf32r(w13v(Wp, k, cINV[r][i]));
}

// ---------------- kernel A1: cross for 2 vertices/block -> g_cross; center slices -> g_M ----------------
__global__ __launch_bounds__(192) void kernA1(const int* __restrict__ nbr_idx,
                                              const float* __restrict__ verts,
                                              const float* __restrict__ fm,
                                              const float* __restrict__ wdim) {
    const int p0 = blockIdx.x * 2;
    const int tid = threadIdx.x;
    __shared__ __align__(16) float s_cross[2][CID * 16];   // [v][ci][n]
    __shared__ __align__(16) float s_wdim[33 * 32];
    __shared__ float s_de[2][96];
    __shared__ int s_nbr[2][16];

    for (int t = tid; t < 33 * 32; t += 192) s_wdim[t] = wdim[t];

    if (tid < 32) {
        int v = tid >> 4, n = tid & 15;
        int p = p0 + v;
        int nb = nbr_idx[p * NN + n];
        s_nbr[v][n] = nb;
        float px = verts[p * 3], py = verts[p * 3 + 1], pz = verts[p * 3 + 2];
        float dx = verts[nb * 3] - px;
        float dy = verts[nb * 3 + 1] - py;
        float dz = verts[nb * 3 + 2] - pz;
        float nrm = sqrtf(dx * dx + dy * dy + dz * dz);
        float inv = 1.0f / fmaxf(nrm, 1e-12f);
        dx *= inv; dy *= inv; dz *= inv;
        const float invn = rsqrtf(2.0f + PHI);
        float d0[12];
#pragma unroll
        for (int q = 0; q < 12; q++)
            d0[q] = (cVSU[q][0] * dx + cVSU[q][1] * dy + cVSU[q][2] * dz) * invn;
#pragma unroll
        for (int col = 0; col < 6; col++)
            s_de[v][n * 6 + col] = fmaxf(d0[cC2V[col][0]], d0[cC2V[col][1]]);
    }
    __syncthreads();

    {
        int v = tid / 96, t0 = tid % 96;
        int n = t0 / 6, i = t0 % 6;
        int nb = s_nbr[v][n];
        u64 acc[16];
#pragma unroll
        for (int q = 0; q < 16; q++) acc[q] = 0ull;
        for (int c = 0; c < 33; c++) {
            float x = (c < 32) ? fm[((size_t)c * VV + nb) * 6 + i] : s_de[v][n * 6 + i];
            u64 xb = bc2(x);
            const u64* wd2 = (const u64*)&s_wdim[c * 32];
#pragma unroll
            for (int q = 0; q < 16; q++) fma2(acc[q], wd2[q], xb);
        }
#pragma unroll
        for (int q = 0; q < 16; q++) {
            float o0, o1; up2(o0, o1, acc[q]);
            s_cross[v][((2 * q)     * 6 + i) * 16 + n] = o0;
            s_cross[v][((2 * q + 1) * 6 + i) * 16 + n] = o1;
        }
    }

    // center (k=12) slices of M for both vertices
    for (int v = 0; v < 2; v++) {
        int c = tid / 6, i = tid % 6;
        float val = fm[((size_t)c * VV + p0 + v) * 6 + i];
        size_t base = (size_t)(p0 + v) * MROW + (size_t)(c * 13 + 12) * 6 + i;
#pragma unroll
        for (int r = 0; r < 12; r++) g_M[base + (size_t)r * EDIM] = val;
    }
    __syncthreads();

    // cooperative coalesced write: 6 warps x 32 rows; 32 consecutive cols (2 vertices x 16 n)
    {
        const int warp = tid >> 5, lane = tid & 31;
        const int v = lane >> 4, n = lane & 15;
        for (int rr = 0; rr < 32; rr++) {
            int ci = warp * 32 + rr;
            g_cross[(size_t)ci * PN + p0 * 16 + lane] = s_cross[v][ci * 16 + n];
        }
    }
}

// ---------------- fused kernel A23: act GEMM + softmax + nfm -> g_M directly ----------------
// Block tile: 128 tasks x 128 pn (= 8 complete vertices). GEMM identical to old A2,
// then act stays in smem: softmax in regs, cross tile reloaded into same smem, nfm -> g_M.
#define KCH 16
#define APAD 136
#define ACTP 132

struct Ph1 {
    float As[2][KCH][APAD];     // 17408 B
    float Bs[2][KCH][APAD];     // 17408 B
    float act[128][ACTP];       // 67584 B
};                              // total 102400 B
#define SMEM_A23 104448         // 192*136*4 (cross tile union)

__global__ __launch_bounds__(256, 2) void kernA23() {
    extern __shared__ __align__(16) char smemRaw[];
    Ph1* S = (Ph1*)smemRaw;
    typedef float CrossRow[APAD];
    CrossRow* cross2 = (CrossRow*)smemRaw;

    const int t0 = blockIdx.y * 128;
    const int c0 = blockIdx.x * 128;
    const int tid = threadIdx.x;

    const int lcol = tid & 127, kh = tid >> 7;   // loader: 8 k-rows each
    const int lane = tid & 31, warp = tid >> 5;
    const int g = lane >> 2, t4 = lane & 3;
    const int wt = (warp & 3) * 32;              // warp t-offset
    const int wp = (warp >> 2) * 64;             // warp pn-offset

    float acc[2][8][4];
#pragma unroll
    for (int mt = 0; mt < 2; mt++)
#pragma unroll
        for (int nt = 0; nt < 8; nt++)
#pragma unroll
            for (int q = 0; q < 4; q++) acc[mt][nt][q] = 0.f;

    // ---- phase 1: GEMM (act tile in fragments) ----
#pragma unroll
    for (int j = 0; j < 8; j++) {
        int k = kh * 8 + j;
        S->As[0][k][lcol] = g_Wdr[(size_t)k * NT + t0 + lcol];
        S->Bs[0][k][lcol] = tf32r(g_cross[(size_t)k * PN + c0 + lcol]);
    }
    __syncthreads();

    const int NCH = CID / KCH;   // 12
    int buf = 0;
    for (int ch = 0; ch < NCH; ch++) {
        float pa[8], pb[8];
        if (ch + 1 < NCH) {
            int k0 = (ch + 1) * KCH;
#pragma unroll
            for (int j = 0; j < 8; j++) {
                int k = kh * 8 + j;
                pa[j] = g_Wdr[(size_t)(k0 + k) * NT + t0 + lcol];
                pb[j] = g_cross[(size_t)(k0 + k) * PN + c0 + lcol];
            }
        }
#pragma unroll
        for (int e = 0; e < 2; e++) {
            const int ks = e * 8;
#pragma unroll
            for (int mt = 0; mt < 2; mt++) {
                int row = wt + mt * 16 + g;
                u32 a0 = __float_as_uint(S->As[buf][ks + t4][row]);
                u32 a1 = __float_as_uint(S->As[buf][ks + t4][row + 8]);
                u32 a2 = __float_as_uint(S->As[buf][ks + t4 + 4][row]);
                u32 a3 = __float_as_uint(S->As[buf][ks + t4 + 4][row + 8]);
#pragma unroll
                for (int nt = 0; nt < 8; nt++) {
                    int col = wp + nt * 8 + g;
                    u32 b0 = __float_as_uint(S->Bs[buf][ks + t4][col]);
                    u32 b1 = __float_as_uint(S->Bs[buf][ks + t4 + 4][col]);
                    mma_tf32(acc[mt][nt], a0, a1, a2, a3, b0, b1);
                }
            }
        }
        __syncthreads();
        if (ch + 1 < NCH) {
            int nb = buf ^ 1;
#pragma unroll
            for (int j = 0; j < 8; j++) {
                int k = kh * 8 + j;
                S->As[nb][k][lcol] = pa[j];
                S->Bs[nb][k][lcol] = tf32r(pb[j]);
            }
            __syncthreads();
        }
        buf ^= 1;
    }

    // ---- fragments -> act smem ----
#pragma unroll
    for (int mt = 0; mt < 2; mt++) {
        int row = wt + mt * 16 + g;
#pragma unroll
        for (int nt = 0; nt < 8; nt++) {
            int col = wp + nt * 8 + 2 * t4;
            *(float2*)&S->act[row][col]     = make_float2(acc[mt][nt][0], acc[mt][nt][1]);
            *(float2*)&S->act[row + 8][col] = make_float2(acc[mt][nt][2], acc[mt][nt][3]);
        }
    }
    __syncthreads();

    // ---- phase 2a: softmax into registers (4 (t,p) pairs per thread) ----
    float a[4][16];
#pragma unroll
    for (int q = 0; q < 4; q++) {
        int idx = tid + 256 * q;
        int tl = idx & 127, p = idx >> 7;
        const float* src = &S->act[tl][p * 16];
#pragma unroll
        for (int j = 0; j < 4; j++) {
            float4 v = *(const float4*)(src + 4 * j);
            a[q][4 * j] = v.x; a[q][4 * j + 1] = v.y; a[q][4 * j + 2] = v.z; a[q][4 * j + 3] = v.w;
        }
        float m = a[q][0];
#pragma unroll
        for (int n = 1; n < 16; n++) m = fmaxf(m, a[q][n]);
        float s = 0.f;
#pragma unroll
        for (int n = 0; n < 16; n++) { a[q][n] = __expf(a[q][n] - m); s += a[q][n]; }
        float invs = 1.0f / s;
#pragma unroll
        for (int n = 0; n < 16; n++) a[q][n] *= invs;
    }
    __syncthreads();

    // ---- phase 2b: load full-precision cross tile into smem (union) ----
#pragma unroll
    for (int j = 0; j < 24; j++) {
        int f4 = tid + 256 * j;              // 6144 float4s = 192 rows x 32
        int row = f4 >> 5, cc4 = (f4 & 31) * 4;
        *(float4*)&cross2[row][cc4] = *(const float4*)&g_cross[(size_t)row * PN + c0 + cc4];
    }
    __syncthreads();

    // ---- phase 2c: nfm -> g_M ----
#pragma unroll
    for (int q = 0; q < 4; q++) {
        int idx = tid + 256 * q;
        int tl = idx & 127, p = idx >> 7;
        int tg = t0 + tl;
        int h = tg / 144, k = (tg / 12) % 12, r = tg % 12;
        int pg = (c0 >> 4) + p;
        size_t base = (size_t)pg * MROW + (size_t)r * EDIM;
#pragma unroll
        for (int cc = 0; cc < 4; cc++) {
            int c = h * 4 + cc;
            float mv[6];
#pragma unroll
            for (int i = 0; i < 6; i++) {
                const float* cp = &cross2[c * 6 + i][p * 16];
                float s0 = 0.f;
#pragma unroll
                for (int n = 0; n < 16; n++) s0 += a[q][n] * cp[n];
                mv[i] = s0;
            }
            float2* dst2 = (float2*)&g_M[base + (size_t)(c * 13 + k) * 6];
            dst2[0] = make_float2(mv[0], mv[1]);
            dst2[1] = make_float2(mv[2], mv[3]);
            dst2[2] = make_float2(mv[4], mv[5]);
        }
    }
}

// ---------------- kernel B (tensor cores): feat[r](64x2048) = Wg[r](64x2496) @ M_r(2496x2048) ----------------
// 128 threads / 4 warps; block tile 64d x 64p; warp tile 32d x 32p (2 m-tiles x 4 n-tiles).
#define BPAD 20
__global__ __launch_bounds__(128) void kernB() {
    const int r  = blockIdx.y;
    const int p1 = blockIdx.x * 64;
    const int tid = threadIdx.x;
    __shared__ __align__(16) float Wt[2][64][BPAD];
    __shared__ __align__(16) float Mt[2][64][BPAD];

    const int lane = tid & 31, warp = tid >> 5;
    const int g = lane >> 2, t4 = lane & 3;
    const int d0w = (warp & 1) * 32;
    const int p0w = (warp >> 1) * 32;

    const int lrow0 = tid >> 2, le0 = tid & 3;
    const int lrow1 = (tid + 128) >> 2, le1 = (tid + 128) & 3;
    const float* wb0 = g_Wg + ((size_t)r * DO + lrow0) * EDIM + le0 * 4;
    const float* wb1 = g_Wg + ((size_t)r * DO + lrow1) * EDIM + le1 * 4;
    const float* mb0 = g_M + (size_t)(p1 + lrow0) * MROW + (size_t)r * EDIM + le0 * 4;
    const float* mb1 = g_M + (size_t)(p1 + lrow1) * MROW + (size_t)r * EDIM + le1 * 4;

    float acc[2][4][4];
#pragma unroll
    for (int mt = 0; mt < 2; mt++)
#pragma unroll
        for (int nt = 0; nt < 4; nt++)
#pragma unroll
            for (int q = 0; q < 4; q++) acc[mt][nt][q] = 0.f;

    {
        float4 w0 = *(const float4*)wb0;
        float4 w1 = *(const float4*)wb1;
        float4 m0 = *(const float4*)mb0;
        float4 m1 = *(const float4*)mb1;
        m0.x = tf32r(m0.x); m0.y = tf32r(m0.y); m0.z = tf32r(m0.z); m0.w = tf32r(m0.w);
        m1.x = tf32r(m1.x); m1.y = tf32r(m1.y); m1.z = tf32r(m1.z); m1.w = tf32r(m1.w);
        *(float4*)&Wt[0][lrow0][le0 * 4] = w0;
        *(float4*)&Wt[0][lrow1][le1 * 4] = w1;
        *(float4*)&Mt[0][lrow0][le0 * 4] = m0;
        *(float4*)&Mt[0][lrow1][le1 * 4] = m1;
    }
    __syncthreads();

    const int NSTEP = EDIM / 16;   // 156
    int buf = 0;
    for (int s = 0; s < NSTEP; s++) {
        float4 w0, w1, m0, m1;
        if (s + 1 < NSTEP) {
            int eo = (s + 1) * 16;
            w0 = *(const float4*)(wb0 + eo);
            w1 = *(const float4*)(wb1 + eo);
            m0 = *(const float4*)(mb0 + eo);
            m1 = *(const float4*)(mb1 + eo);
        }
#pragma unroll
        for (int kk = 0; kk < 2; kk++) {
            const int e = kk * 8 + t4;
#pragma unroll
            for (int mt = 0; mt < 2; mt++) {
                const int ar = d0w + mt * 16 + g;
                u32 a0 = __float_as_uint(Wt[buf][ar][e]);
                u32 a1 = __float_as_uint(Wt[buf][ar + 8][e]);
                u32 a2 = __float_as_uint(Wt[buf][ar][e + 4]);
                u32 a3 = __float_as_uint(Wt[buf][ar + 8][e + 4]);
#pragma unroll
                for (int nt = 0; nt < 4; nt++) {
                    const int br = p0w + nt * 8 + g;
                    u32 b0 = __float_as_uint(Mt[buf][br][e]);
                    u32 b1 = __float_as_uint(Mt[buf][br][e + 4]);
                    mma_tf32(acc[mt][nt], a0, a1, a2, a3, b0, b1);
                }
            }
        }
        __syncthreads();
        if (s + 1 < NSTEP) {
            int nb = buf ^ 1;
            m0.x = tf32r(m0.x); m0.y = tf32r(m0.y); m0.z = tf32r(m0.z); m0.w = tf32r(m0.w);
            m1.x = tf32r(m1.x); m1.y = tf32r(m1.y); m1.z = tf32r(m1.z); m1.w = tf32r(m1.w);
            *(float4*)&Wt[nb][lrow0][le0 * 4] = w0;
            *(float4*)&Wt[nb][lrow1][le1 * 4] = w1;
            *(float4*)&Mt[nb][lrow0][le0 * 4] = m0;
            *(float4*)&Mt[nb][lrow1][le1 * 4] = m1;
            __syncthreads();
        }
        buf ^= 1;
    }

#pragma unroll
    for (int mt = 0; mt < 2; mt++) {
#pragma unroll
        for (int nt = 0; nt < 4; nt++) {
            int pcol = p1 + p0w + nt * 8 + 2 * t4;
            int drow = d0w + mt * 16 + g;
            float* f0 = &g_feat[((size_t)r * DO + drow) * VV + pcol];
            float* f1 = &g_feat[((size_t)r * DO + drow + 8) * VV + pcol];
            *(float2*)f0 = make_float2(acc[mt][nt][0], acc[mt][nt][1]);
            *(float2*)f1 = make_float2(acc[mt][nt][2], acc[mt][nt][3]);
        }
    }
}

// ---------------- kernel C: ka = max over C2V pairs of feat ----------------
__global__ void kernC(float* __restrict__ out) {
    int idx = blockIdx.x * blockDim.x + threadIdx.x;   // over DO*VV
    if (idx >= DO * VV) return;
    int d = idx / VV, p = idx % VV;
#pragma unroll
    for (int col = 0; col < 6; col++) {
        int r0 = cC2V[col][0], r1 = cC2V[col][1];
        float v = fmaxf(g_feat[((size_t)r0 * DO + d) * VV + p],
                        g_feat[((size_t)r1 * DO + d) * VV + p]);
        out[(size_t)idx * 6 + col] = v;
    }
}

extern "C" void kernel_launch(void* const* d_in, const int* in_sizes, int n_in,
                              void* d_out, int out_size) {
    const int*   nbr   = (const int*)d_in[0];
    const float* verts = (const float*)d_in[1];
    const float* fm    = (const float*)d_in[2];
    const float* wdim  = (const float*)d_in[3];
    const float* W     = (const float*)d_in[4];
    const float* Wdir  = (const float*)d_in[5];
    float* out = (float*)d_out;

    cudaFuncSetAttribute(kernA23, cudaFuncAttributeMaxDynamicSharedMemorySize, SMEM_A23);

    prepWdr<<<(CID * NT + 255) / 256, 256>>>(Wdir);
    prepWg<<<(12 * DO * EDIM + 255) / 256, 256>>>(W);
    kernA1<<<VV / 2, 192>>>(nbr, verts, fm, wdim);
    {
        dim3 ga(PN / 128, NT / 128);           // 256 x 9
        kernA23<<<ga, 256, SMEM_A23>>>();
    }
    {
        dim3 gb(VV / 64, 12);
        kernB<<<gb, 128>>>();
    }
    kernC<<<(DO * VV + 255) / 256, 256>>>(out);
    if (out_size >= KA_ELEMS + FM_ELEMS) {
        cudaMemcpyAsync(out + KA_ELEMS, fm, (size_t)FM_ELEMS * sizeof(float),
                        cudaMemcpyDeviceToDevice, 0);
    }
}